// round 2
// baseline (speedup 1.0000x reference)
#include <cuda_runtime.h>
#include <math.h>
#include <stdint.h>

#define NB 2
#define NN 256
#define DD 256
#define NH 8
#define FFD 1024

// scratch (static device globals; no allocation)
__device__ float g_x [NB*NN*DD];
__device__ float g_nq[NB*NN*DD];
__device__ float g_sc[(size_t)NB*NH*NN*NN];
__device__ float g_ao[NB*NN*DD];
__device__ float g_r [NB*NN*DD];
__device__ float g_x2[NB*NN*DD];
__device__ float g_hg[NB*NN*FFD];

// ---- f32x2 helpers ----
__device__ __forceinline__ unsigned long long dup2(float x) {
    unsigned long long r;
    asm("mov.b64 %0, {%1, %1};" : "=l"(r) : "f"(x));
    return r;
}
__device__ __forceinline__ void fma2(unsigned long long &d,
                                     unsigned long long a, unsigned long long b) {
    asm("fma.rn.f32x2 %0, %1, %2, %0;" : "+l"(d) : "l"(a), "l"(b));
}
__device__ __forceinline__ void unpack2(unsigned long long v, float &lo, float &hi) {
    asm("mov.b64 {%0, %1}, %2;" : "=f"(lo), "=f"(hi) : "l"(v));
}

// ---- LayerNorm: one row (256 elems) per block ----
__global__ void ln_kernel(const float* __restrict__ in,
                          const float* __restrict__ gam,
                          const float* __restrict__ bet,
                          float* __restrict__ out) {
    __shared__ float sh[16];
    __shared__ float stats[2];
    const int row = blockIdx.x, t = threadIdx.x;
    float v = in[(size_t)row * DD + t];
    float s = v, sq = v * v;
    #pragma unroll
    for (int o = 16; o; o >>= 1) {
        s  += __shfl_down_sync(0xffffffffu, s,  o);
        sq += __shfl_down_sync(0xffffffffu, sq, o);
    }
    if ((t & 31) == 0) { sh[t >> 5] = s; sh[(t >> 5) + 8] = sq; }
    __syncthreads();
    if (t == 0) {
        float ts = 0.f, tq = 0.f;
        #pragma unroll
        for (int k = 0; k < 8; ++k) { ts += sh[k]; tq += sh[k + 8]; }
        float mu = ts * (1.0f / 256.0f);
        float var = tq * (1.0f / 256.0f) - mu * mu;
        stats[0] = mu; stats[1] = rsqrtf(var + 1e-5f);
    }
    __syncthreads();
    out[(size_t)row * DD + t] = (v - stats[0]) * stats[1] * gam[t] + bet[t];
}

// ---- generic 64x32 fp32 GEMM tile; 256 threads ----
__device__ __forceinline__ void gemm_tile64x32(
    const float* __restrict__ A, const float* __restrict__ B,
    int lda, int ldb, int K, int m0, int n0, float acc[8]) {
    __shared__ __align__(16) float AsT[32][68];   // k x m
    __shared__ float Bs[32][33];                  // k x n
    const int t = threadIdx.x, tn = t & 31, tg = t >> 5;
    #pragma unroll
    for (int q = 0; q < 8; ++q) acc[q] = 0.f;
    for (int k0 = 0; k0 < K; k0 += 32) {
        #pragma unroll
        for (int ph = 0; ph < 2; ++ph) {
            int flat = t + 256 * ph;
            int m = flat >> 3, kc = (flat & 7) << 2;
            float4 av = *(const float4*)(A + (size_t)(m0 + m) * lda + k0 + kc);
            AsT[kc + 0][m] = av.x; AsT[kc + 1][m] = av.y;
            AsT[kc + 2][m] = av.z; AsT[kc + 3][m] = av.w;
        }
        {
            int kr = t >> 3, nc = (t & 7) << 2;
            float4 bv = *(const float4*)(B + (size_t)(k0 + kr) * ldb + n0 + nc);
            Bs[kr][nc + 0] = bv.x; Bs[kr][nc + 1] = bv.y;
            Bs[kr][nc + 2] = bv.z; Bs[kr][nc + 3] = bv.w;
        }
        __syncthreads();
        #pragma unroll
        for (int kk = 0; kk < 32; ++kk) {
            float4 a0 = *(const float4*)&AsT[kk][tg * 8];
            float4 a1 = *(const float4*)&AsT[kk][tg * 8 + 4];
            float bb = Bs[kk][tn];
            acc[0] = fmaf(a0.x, bb, acc[0]); acc[1] = fmaf(a0.y, bb, acc[1]);
            acc[2] = fmaf(a0.z, bb, acc[2]); acc[3] = fmaf(a0.w, bb, acc[3]);
            acc[4] = fmaf(a1.x, bb, acc[4]); acc[5] = fmaf(a1.y, bb, acc[5]);
            acc[6] = fmaf(a1.z, bb, acc[6]); acc[7] = fmaf(a1.w, bb, acc[7]);
        }
        __syncthreads();
    }
}

__global__ __launch_bounds__(256) void gemm_bias(
    const float* __restrict__ A, const float* __restrict__ B,
    const float* __restrict__ bias, float* __restrict__ C,
    int lda, int ldb, int ldc, int K) {
    float acc[8];
    const int m0 = blockIdx.x * 64, n0 = blockIdx.y * 32;
    gemm_tile64x32(A, B, lda, ldb, K, m0, n0, acc);
    const int tn = threadIdx.x & 31, tg = threadIdx.x >> 5;
    const float bb = bias[n0 + tn];
    #pragma unroll
    for (int q = 0; q < 8; ++q)
        C[(size_t)(m0 + tg * 8 + q) * ldc + n0 + tn] = acc[q] + bb;
}

__global__ __launch_bounds__(256) void gemm_bias_res(
    const float* __restrict__ A, const float* __restrict__ B,
    const float* __restrict__ bias, const float* __restrict__ R,
    float* __restrict__ C, int lda, int ldb, int ldc, int K) {
    float acc[8];
    const int m0 = blockIdx.x * 64, n0 = blockIdx.y * 32;
    gemm_tile64x32(A, B, lda, ldb, K, m0, n0, acc);
    const int tn = threadIdx.x & 31, tg = threadIdx.x >> 5;
    const float bb = bias[n0 + tn];
    #pragma unroll
    for (int q = 0; q < 8; ++q) {
        size_t idx = (size_t)(m0 + tg * 8 + q) * ldc + n0 + tn;
        C[idx] = acc[q] + bb + R[idx];
    }
}

__global__ __launch_bounds__(256) void gemm_gelu(
    const float* __restrict__ A, const float* __restrict__ B,
    const float* __restrict__ bias, float* __restrict__ C,
    int lda, int ldb, int ldc, int K) {
    float acc[8];
    const int m0 = blockIdx.x * 64, n0 = blockIdx.y * 32;
    gemm_tile64x32(A, B, lda, ldb, K, m0, n0, acc);
    const int tn = threadIdx.x & 31, tg = threadIdx.x >> 5;
    const float bb = bias[n0 + tn];
    #pragma unroll
    for (int q = 0; q < 8; ++q) {
        float v = acc[q] + bb;
        C[(size_t)(m0 + tg * 8 + q) * ldc + n0 + tn] =
            0.5f * v * (1.0f + erff(v * 0.70710678118654752f));
    }
}

// attn @ V, per (b,h): A = attn[b,h] (256x256), B = nq[b,:,h*32:h*32+32]
__global__ __launch_bounds__(256) void attnv_kernel(
    const float* __restrict__ scores, const float* __restrict__ nq,
    float* __restrict__ ao) {
    const int z = blockIdx.z, b = z >> 3, h = z & 7;
    const float* A = scores + (size_t)z * NN * NN;
    const float* B = nq + (size_t)b * NN * DD + h * 32;
    float acc[8];
    const int m0 = blockIdx.x * 64;
    gemm_tile64x32(A, B, NN, DD, NN, m0, 0, acc);
    const int tn = threadIdx.x & 31, tg = threadIdx.x >> 5;
    #pragma unroll
    for (int q = 0; q < 8; ++q)
        ao[((size_t)b * NN + (m0 + tg * 8 + q)) * DD + h * 32 + tn] = acc[q];
}

// ---- heavy fused kernel: edges@W + bias -> head scores -> 10*tanh ----
// grid (jt=4, i=256, b=2), 256 threads. Thread (tx=t&31, ty=t>>5):
// outputs o in {tx*4..tx*4+3} U {128+tx*4..128+tx*4+3}, j rows ty*8..ty*8+7.
__global__ __launch_bounds__(256, 2) void edge_kernel(
    const float* __restrict__ edges, const float* __restrict__ W,
    const float* __restrict__ bvec, const float* __restrict__ nq,
    float* __restrict__ scores) {
    __shared__ __align__(16) float At[16][68];
    __shared__ __align__(16) float Ws[16][256];
    const int t = threadIdx.x, tx = t & 31, ty = t >> 5;
    const int jt = blockIdx.x, i = blockIdx.y, bz = blockIdx.z;
    const int oA = tx * 4, oB = 128 + tx * 4;
    const float* Arow = edges + (((size_t)(bz * NN + i)) * NN + jt * 64) * DD;

    unsigned long long acc[8][4];
    #pragma unroll
    for (int a = 0; a < 8; ++a) { acc[a][0]=0; acc[a][1]=0; acc[a][2]=0; acc[a][3]=0; }

    const int jl = t >> 2, q4 = (t & 3) * 4;
    for (int k0 = 0; k0 < DD; k0 += 16) {
        float4 ev = *(const float4*)(Arow + (size_t)jl * DD + k0 + q4);
        At[q4 + 0][jl] = ev.x; At[q4 + 1][jl] = ev.y;
        At[q4 + 2][jl] = ev.z; At[q4 + 3][jl] = ev.w;
        #pragma unroll
        for (int ph = 0; ph < 4; ++ph) {
            int flat = t + 256 * ph;
            int kr = flat >> 6, oc = (flat & 63) << 2;
            *(float4*)&Ws[kr][oc] = *(const float4*)(W + (size_t)(k0 + kr) * DD + oc);
        }
        __syncthreads();
        #pragma unroll
        for (int kk = 0; kk < 16; ++kk) {
            const float4 a0 = *(const float4*)&At[kk][ty * 8];
            const float4 a1 = *(const float4*)&At[kk][ty * 8 + 4];
            unsigned long long A2[8];
            A2[0]=dup2(a0.x); A2[1]=dup2(a0.y); A2[2]=dup2(a0.z); A2[3]=dup2(a0.w);
            A2[4]=dup2(a1.x); A2[5]=dup2(a1.y); A2[6]=dup2(a1.z); A2[7]=dup2(a1.w);
            const ulonglong2 bA = *(const ulonglong2*)&Ws[kk][oA];
            const ulonglong2 bB = *(const ulonglong2*)&Ws[kk][oB];
            #pragma unroll
            for (int a = 0; a < 8; ++a) {
                fma2(acc[a][0], A2[a], bA.x);
                fma2(acc[a][1], A2[a], bA.y);
                fma2(acc[a][2], A2[a], bB.x);
                fma2(acc[a][3], A2[a], bB.y);
            }
        }
        __syncthreads();
    }

    float biasA[4], biasB[4], nqiA[4], nqiB[4];
    {
        float4 v;
        v = *(const float4*)(bvec + oA); biasA[0]=v.x; biasA[1]=v.y; biasA[2]=v.z; biasA[3]=v.w;
        v = *(const float4*)(bvec + oB); biasB[0]=v.x; biasB[1]=v.y; biasB[2]=v.z; biasB[3]=v.w;
        const float* nqi = nq + ((size_t)bz * NN + i) * DD;
        v = *(const float4*)(nqi + oA); nqiA[0]=v.x; nqiA[1]=v.y; nqiA[2]=v.z; nqiA[3]=v.w;
        v = *(const float4*)(nqi + oB); nqiB[0]=v.x; nqiB[1]=v.y; nqiB[2]=v.z; nqiB[3]=v.w;
    }
    const float invs = 0.17677669529663687f;  // 1/sqrt(32)
    #pragma unroll
    for (int a = 0; a < 8; ++a) {
        const int jg = jt * 64 + ty * 8 + a;
        const float* nqj = nq + ((size_t)bz * NN + jg) * DD;
        float4 r0 = *(const float4*)(nqj + oA);
        float4 r1 = *(const float4*)(nqj + oB);
        float jA[4] = { r0.x, r0.y, r0.z, r0.w };
        float jB[4] = { r1.x, r1.y, r1.z, r1.w };
        float eA[4], eB[4];
        unpack2(acc[a][0], eA[0], eA[1]); unpack2(acc[a][1], eA[2], eA[3]);
        unpack2(acc[a][2], eB[0], eB[1]); unpack2(acc[a][3], eB[2], eB[3]);
        float sA = 0.f, sB = 0.f;
        #pragma unroll
        for (int c = 0; c < 4; ++c) {
            float ea = eA[c] + biasA[c];
            float eb = eB[c] + biasB[c];
            sA += (ea + nqiA[c]) * (ea + jA[c]);
            sB += (eb + nqiB[c]) * (eb + jB[c]);
        }
        #pragma unroll
        for (int o = 1; o < 8; o <<= 1) {
            sA += __shfl_xor_sync(0xffffffffu, sA, o);
            sB += __shfl_xor_sync(0xffffffffu, sB, o);
        }
        if ((tx & 7) == 0) {
            const int g = tx >> 3;
            scores[(((size_t)bz * NH + g    ) * NN + i) * NN + jg] = 10.0f * tanhf(sA * invs);
            scores[(((size_t)bz * NH + g + 4) * NN + i) * NN + jg] = 10.0f * tanhf(sB * invs);
        }
    }
}

// ---- softmax over last dim (256), in place ----
__global__ void softmax_kernel(float* __restrict__ sc) {
    __shared__ float sh[8];
    __shared__ float red;
    const size_t row = blockIdx.x;
    const int t = threadIdx.x;
    float v = sc[row * NN + t];
    float m = v;
    #pragma unroll
    for (int o = 16; o; o >>= 1) m = fmaxf(m, __shfl_xor_sync(0xffffffffu, m, o));
    if ((t & 31) == 0) sh[t >> 5] = m;
    __syncthreads();
    if (t == 0) {
        float mm = sh[0];
        #pragma unroll
        for (int w = 1; w < 8; ++w) mm = fmaxf(mm, sh[w]);
        red = mm;
    }
    __syncthreads();
    m = red;
    float e = expf(v - m);
    float s = e;
    #pragma unroll
    for (int o = 16; o; o >>= 1) s += __shfl_xor_sync(0xffffffffu, s, o);
    __syncthreads();
    if ((t & 31) == 0) sh[t >> 5] = s;
    __syncthreads();
    if (t == 0) {
        float ss = 0.f;
        #pragma unroll
        for (int w = 0; w < 8; ++w) ss += sh[w];
        red = 1.0f / ss;
    }
    __syncthreads();
    sc[row * NN + t] = e * red;
}

extern "C" void kernel_launch(void* const* d_in, const int* in_sizes, int n_in,
                              void* d_out, int out_size) {
    const float* nodes = (const float*)d_in[0];
    const float* edges = (const float*)d_in[1];
    const float* W     = (const float*)d_in[2];
    const float* b     = (const float*)d_in[3];
    const float* ln_g  = (const float*)d_in[4];
    const float* ln_b  = (const float*)d_in[5];
    const float* W1    = (const float*)d_in[6];
    const float* b1    = (const float*)d_in[7];
    const float* W2    = (const float*)d_in[8];
    const float* b2    = (const float*)d_in[9];
    float* out = (float*)d_out;

    float *px, *pnq, *psc, *pao, *pr, *px2, *phg;
    cudaGetSymbolAddress((void**)&px,  g_x);
    cudaGetSymbolAddress((void**)&pnq, g_nq);
    cudaGetSymbolAddress((void**)&psc, g_sc);
    cudaGetSymbolAddress((void**)&pao, g_ao);
    cudaGetSymbolAddress((void**)&pr,  g_r);
    cudaGetSymbolAddress((void**)&px2, g_x2);
    cudaGetSymbolAddress((void**)&phg, g_hg);

    ln_kernel<<<NB * NN, 256>>>(nodes, ln_g, ln_b, px);
    gemm_bias<<<dim3(8, 8), 256>>>(px, W, b, pnq, DD, DD, DD, DD);
    edge_kernel<<<dim3(4, NN, NB), 256>>>(edges, W, b, pnq, psc);
    softmax_kernel<<<NB * NH * NN, 256>>>(psc);
    attnv_kernel<<<dim3(4, 1, NB * NH), 256>>>(psc, pnq, pao);
    gemm_bias_res<<<dim3(8, 8), 256>>>(pao, W, b, px, pr, DD, DD, DD, DD);
    ln_kernel<<<NB * NN, 256>>>(pr, ln_g, ln_b, px2);
    gemm_gelu<<<dim3(8, 32), 256>>>(px2, W1, b1, phg, DD, FFD, FFD, DD);
    gemm_bias_res<<<dim3(8, 8), 256>>>(phg, W2, b2, px2, out, FFD, DD, DD, FFD);
}

// round 9
// speedup vs baseline: 1.4021x; 1.4021x over previous
#include <cuda_runtime.h>
#include <cuda_fp16.h>
#include <cuda_bf16.h>
#include <math.h>
#include <stdint.h>

#define NB 2
#define NN 256
#define DD 256
#define NH 8
#define FFD 1024

// ---------------- scratch (static device globals) ----------------
__device__ float g_x [NB*NN*DD];
__device__ float g_nq[NB*NN*DD];
__device__ float g_sc[(size_t)NB*NH*NN*NN];
__device__ float g_ao[NB*NN*DD];
__device__ float g_r [NB*NN*DD];
__device__ float g_x2[NB*NN*DD];
__device__ float g_hg[NB*NN*FFD];
__device__ __half g_wq[4*256*128];   // packed W fragments: 256 KB

// ---------------- cp.async helpers ----------------
__device__ __forceinline__ uint32_t smem_u32(const void* p) {
    uint32_t a;
    asm("{ .reg .u64 t; cvta.to.shared.u64 t, %1; cvt.u32.u64 %0, t; }" : "=r"(a) : "l"(p));
    return a;
}
#define CP16(dst, src) \
    asm volatile("cp.async.cg.shared.global [%0], [%1], 16;" :: "r"(dst), "l"(src))
#define CP_COMMIT() asm volatile("cp.async.commit_group;" ::: "memory")
#define CP_WAIT(n)  asm volatile("cp.async.wait_group %0;" :: "n"(n) : "memory")

// ---------------- mma.sync m16n8k16 fp16 -> fp32 ----------------
__device__ __forceinline__ void mma16816(float* acc, uint32_t a0, uint32_t a1,
                                         uint32_t a2, uint32_t a3,
                                         uint32_t b0, uint32_t b1) {
    asm volatile(
        "mma.sync.aligned.m16n8k16.row.col.f32.f16.f16.f32 "
        "{%0,%1,%2,%3}, {%4,%5,%6,%7}, {%8,%9}, {%0,%1,%2,%3};"
        : "+f"(acc[0]), "+f"(acc[1]), "+f"(acc[2]), "+f"(acc[3])
        : "r"(a0), "r"(a1), "r"(a2), "r"(a3), "r"(b0), "r"(b1));
}

__device__ __forceinline__ void split_f2(float2 v, uint32_t &hi, uint32_t &lo) {
    __half hx = __float2half_rn(v.x), hy = __float2half_rn(v.y);
    __half lx = __float2half_rn(v.x - __half2float(hx));
    __half ly = __float2half_rn(v.y - __half2float(hy));
    hi = (uint32_t)__half_as_ushort(hx) | ((uint32_t)__half_as_ushort(hy) << 16);
    lo = (uint32_t)__half_as_ushort(lx) | ((uint32_t)__half_as_ushort(ly) << 16);
}

// ---------------- prep W: pack W^T hi/lo into fragment-friendly 16B units ----
// unit(c, n, s, p): halves [hi(ka),hi(ka+1),hi(ka+8),hi(ka+9), lo same] where
// ka = c*64 + s*16 + p*2, element = W[ka + delta][n].  16384 units total.
__global__ void prep_w(const float* __restrict__ W, __half* __restrict__ wq) {
    int id = blockIdx.x * 256 + threadIdx.x;     // 16384
    int p = id & 3, s = (id >> 2) & 3, n = (id >> 4) & 255, c = id >> 12;
    int ka = c * 64 + s * 16 + p * 2;
    __half u[8];
    #pragma unroll
    for (int q = 0; q < 4; ++q) {
        int k = ka + (q >> 1) * 8 + (q & 1);
        float v = W[k * 256 + n];
        __half h = __float2half_rn(v);
        u[q] = h;
        u[q + 4] = __float2half_rn(v - __half2float(h));
    }
    *(uint4*)(wq + (size_t)id * 8) = *(uint4*)u;
}

// ---------------- fused edge GEMM (mma.sync fp16x3) + score epilogue -------
// grid (jt=2, i=256, b=2), 256 threads (8 warps). CTA: 128 edge rows x 256 cols.
#define A_STAGE 34816            // 128 rows x 272B (64 fp32 + pad)
#define B_STAGE 69632            // 256 n x 272B (4 ksteps x 4 pairs x 16B + pad)
#define B_BASE  (2*A_STAGE)
#define MISC    (B_BASE + 2*B_STAGE)
#define EDGE_SMEM (MISC + 2048)

__global__ __launch_bounds__(256, 1) void edge_mma_kernel(
    const float* __restrict__ edges, const __half* __restrict__ wq,
    const float* __restrict__ bias, const float* __restrict__ nq,
    float* __restrict__ scores) {
    extern __shared__ char smem[];
    const uint32_t sb = smem_u32(smem);
    const int t = threadIdx.x, lane = t & 31, w = t >> 5;
    const int qp = lane & 3, lg = lane >> 2;
    const int jt = blockIdx.x, i = blockIdx.y, b = blockIdx.z;
    const size_t r0 = ((size_t)(b * NN + i)) * NN + jt * 128;
    const char* eg = (const char*)(edges + r0 * DD);
    const char* wg = (const char*)wq;

    // stage bias + nq_i
    float* sBias = (float*)(smem + MISC);
    float* sNqi  = sBias + 256;
    sBias[t] = bias[t];
    sNqi[t]  = nq[((size_t)(b * NN + i)) * DD + t];

    // prefetch chunks 0,1
    #pragma unroll
    for (int c = 0; c < 2; ++c) {
        uint32_t a_s = sb + c * A_STAGE;
        #pragma unroll
        for (int it = 0; it < 8; ++it) {
            int u = t + 256 * it, row = u >> 4, part = u & 15;
            CP16(a_s + row * 272 + part * 16, eg + (size_t)row * 1024 + c * 256 + part * 16);
        }
        uint32_t b_s = sb + B_BASE + c * B_STAGE;
        #pragma unroll
        for (int it = 0; it < 16; ++it) {
            int u = t + 256 * it, n = u >> 4, part = u & 15;
            CP16(b_s + n * 272 + part * 16, wg + c * 65536 + n * 256 + part * 16);
        }
        CP_COMMIT();
    }

    const int r1 = w * 16 + lg;            // CTA-local row
    float acc[128];                        // [h][nt][4]
    #pragma unroll
    for (int q = 0; q < 128; ++q) acc[q] = 0.f;

    for (int c = 0; c < 4; ++c) {
        if (c < 3) { CP_WAIT(1); } else { CP_WAIT(0); }
        __syncthreads();
        const int buf = c & 1;
        const char* abase = smem + buf * A_STAGE;
        const char* bbase = smem + B_BASE + buf * B_STAGE;

        // build A fragments (fp32 -> fp16 hi/lo)
        uint32_t AH[4][4], AL[4][4];
        #pragma unroll
        for (int s = 0; s < 4; ++s) {
            int col = s * 16 + qp * 2;
            float2 va = *(const float2*)(abase + r1 * 272 + col * 4);
            float2 vb = *(const float2*)(abase + (r1 + 8) * 272 + col * 4);
            float2 vc = *(const float2*)(abase + r1 * 272 + (col + 8) * 4);
            float2 vd = *(const float2*)(abase + (r1 + 8) * 272 + (col + 8) * 4);
            split_f2(va, AH[s][0], AL[s][0]);
            split_f2(vb, AH[s][1], AL[s][1]);
            split_f2(vc, AH[s][2], AL[s][2]);
            split_f2(vd, AH[s][3], AL[s][3]);
        }
        #pragma unroll
        for (int h = 0; h < 8; ++h) {
            #pragma unroll
            for (int nt = 0; nt < 4; ++nt) {
                float* ac = &acc[h * 16 + nt * 4];
                const int n = h * 32 + nt * 8 + lg;
                #pragma unroll
                for (int s = 0; s < 4; ++s) {
                    uint4 v = *(const uint4*)(bbase + n * 272 + s * 64 + qp * 16);
                    mma16816(ac, AH[s][0], AH[s][1], AH[s][2], AH[s][3], v.x, v.y);
                    mma16816(ac, AH[s][0], AH[s][1], AH[s][2], AH[s][3], v.z, v.w);
                    mma16816(ac, AL[s][0], AL[s][1], AL[s][2], AL[s][3], v.x, v.y);
                }
            }
        }
        __syncthreads();
        if (c < 2) {   // stage chunk c+2 into buf
            int cn = c + 2;
            uint32_t a_s = sb + buf * A_STAGE;
            #pragma unroll
            for (int it = 0; it < 8; ++it) {
                int u = t + 256 * it, row = u >> 4, part = u & 15;
                CP16(a_s + row * 272 + part * 16, eg + (size_t)row * 1024 + cn * 256 + part * 16);
            }
            uint32_t b_s = sb + B_BASE + buf * B_STAGE;
            #pragma unroll
            for (int it = 0; it < 16; ++it) {
                int u = t + 256 * it, n = u >> 4, part = u & 15;
                CP16(b_s + n * 272 + part * 16, wg + cn * 65536 + n * 256 + part * 16);
            }
            CP_COMMIT();
        }
    }

    // epilogue: per-head score reduction
    const int j1 = jt * 128 + r1, j2 = j1 + 8;
    const float* nqb = nq + ((size_t)b * NN) * DD;
    const float invs = 0.17677669529663687f;   // 1/sqrt(32)
    #pragma unroll
    for (int h = 0; h < 8; ++h) {
        float s1 = 0.f, s2 = 0.f;
        #pragma unroll
        for (int nt = 0; nt < 4; ++nt) {
            const int col = h * 32 + nt * 8 + qp * 2;
            float2 q1 = *(const float2*)(nqb + (size_t)j1 * DD + col);
            float2 q2 = *(const float2*)(nqb + (size_t)j2 * DD + col);
            float bi0 = sBias[col], bi1 = sBias[col + 1];
            float ni0 = sNqi[col],  ni1 = sNqi[col + 1];
            const float* a = &acc[h * 16 + nt * 4];
            float e;
            e = a[0] + bi0; s1 += (e + ni0) * (e + q1.x);
            e = a[1] + bi1; s1 += (e + ni1) * (e + q1.y);
            e = a[2] + bi0; s2 += (e + ni0) * (e + q2.x);
            e = a[3] + bi1; s2 += (e + ni1) * (e + q2.y);
        }
        s1 += __shfl_xor_sync(0xffffffffu, s1, 1);
        s1 += __shfl_xor_sync(0xffffffffu, s1, 2);
        s2 += __shfl_xor_sync(0xffffffffu, s2, 1);
        s2 += __shfl_xor_sync(0xffffffffu, s2, 2);
        if (qp == 0) {
            float* sp = scores + (((size_t)(b * NH + h)) << 16) + (size_t)i * NN;
            sp[j1] = 10.0f * tanhf(s1 * invs);
            sp[j2] = 10.0f * tanhf(s2 * invs);
        }
    }
}

// ---------------- LayerNorm ----------------
__global__ void ln_kernel(const float* __restrict__ in,
                          const float* __restrict__ gam,
                          const float* __restrict__ bet,
                          float* __restrict__ out) {
    __shared__ float sh[16];
    __shared__ float stats[2];
    const int row = blockIdx.x, t = threadIdx.x;
    float v = in[(size_t)row * DD + t];
    float s = v, sq = v * v;
    #pragma unroll
    for (int o = 16; o; o >>= 1) {
        s  += __shfl_down_sync(0xffffffffu, s,  o);
        sq += __shfl_down_sync(0xffffffffu, sq, o);
    }
    if ((t & 31) == 0) { sh[t >> 5] = s; sh[(t >> 5) + 8] = sq; }
    __syncthreads();
    if (t == 0) {
        float ts = 0.f, tq = 0.f;
        #pragma unroll
        for (int k = 0; k < 8; ++k) { ts += sh[k]; tq += sh[k + 8]; }
        float mu = ts * (1.0f / 256.0f);
        float var = tq * (1.0f / 256.0f) - mu * mu;
        stats[0] = mu; stats[1] = rsqrtf(var + 1e-5f);
    }
    __syncthreads();
    out[(size_t)row * DD + t] = (v - stats[0]) * stats[1] * gam[t] + bet[t];
}

// ---------------- fp32 64x32 GEMM tile for the small GEMMs ----------------
__device__ __forceinline__ void gemm_tile64x32(
    const float* __restrict__ A, const float* __restrict__ B,
    int lda, int ldb, int K, int m0, int n0, float acc[8]) {
    __shared__ __align__(16) float AsT[32][68];
    __shared__ float Bs[32][33];
    const int t = threadIdx.x, tn = t & 31, tg = t >> 5;
    #pragma unroll
    for (int q = 0; q < 8; ++q) acc[q] = 0.f;
    for (int k0 = 0; k0 < K; k0 += 32) {
        #pragma unroll
        for (int ph = 0; ph < 2; ++ph) {
            int flat = t + 256 * ph;
            int m = flat >> 3, kc = (flat & 7) << 2;
            float4 av = *(const float4*)(A + (size_t)(m0 + m) * lda + k0 + kc);
            AsT[kc + 0][m] = av.x; AsT[kc + 1][m] = av.y;
            AsT[kc + 2][m] = av.z; AsT[kc + 3][m] = av.w;
        }
        {
            int kr = t >> 3, nc = (t & 7) << 2;
            float4 bv = *(const float4*)(B + (size_t)(k0 + kr) * ldb + n0 + nc);
            Bs[kr][nc + 0] = bv.x; Bs[kr][nc + 1] = bv.y;
            Bs[kr][nc + 2] = bv.z; Bs[kr][nc + 3] = bv.w;
        }
        __syncthreads();
        #pragma unroll
        for (int kk = 0; kk < 32; ++kk) {
            float4 a0 = *(const float4*)&AsT[kk][tg * 8];
            float4 a1 = *(const float4*)&AsT[kk][tg * 8 + 4];
            float bb = Bs[kk][tn];
            acc[0] = fmaf(a0.x, bb, acc[0]); acc[1] = fmaf(a0.y, bb, acc[1]);
            acc[2] = fmaf(a0.z, bb, acc[2]); acc[3] = fmaf(a0.w, bb, acc[3]);
            acc[4] = fmaf(a1.x, bb, acc[4]); acc[5] = fmaf(a1.y, bb, acc[5]);
            acc[6] = fmaf(a1.z, bb, acc[6]); acc[7] = fmaf(a1.w, bb, acc[7]);
        }
        __syncthreads();
    }
}

__global__ __launch_bounds__(256) void gemm_bias(
    const float* __restrict__ A, const float* __restrict__ B,
    const float* __restrict__ bias, float* __restrict__ C,
    int lda, int ldb, int ldc, int K) {
    float acc[8];
    const int m0 = blockIdx.x * 64, n0 = blockIdx.y * 32;
    gemm_tile64x32(A, B, lda, ldb, K, m0, n0, acc);
    const int tn = threadIdx.x & 31, tg = threadIdx.x >> 5;
    const float bb = bias[n0 + tn];
    #pragma unroll
    for (int q = 0; q < 8; ++q)
        C[(size_t)(m0 + tg * 8 + q) * ldc + n0 + tn] = acc[q] + bb;
}

__global__ __launch_bounds__(256) void gemm_bias_res(
    const float* __restrict__ A, const float* __restrict__ B,
    const float* __restrict__ bias, const float* __restrict__ R,
    float* __restrict__ C, int lda, int ldb, int ldc, int K) {
    float acc[8];
    const int m0 = blockIdx.x * 64, n0 = blockIdx.y * 32;
    gemm_tile64x32(A, B, lda, ldb, K, m0, n0, acc);
    const int tn = threadIdx.x & 31, tg = threadIdx.x >> 5;
    const float bb = bias[n0 + tn];
    #pragma unroll
    for (int q = 0; q < 8; ++q) {
        size_t idx = (size_t)(m0 + tg * 8 + q) * ldc + n0 + tn;
        C[idx] = acc[q] + bb + R[idx];
    }
}

__global__ __launch_bounds__(256) void gemm_gelu(
    const float* __restrict__ A, const float* __restrict__ B,
    const float* __restrict__ bias, float* __restrict__ C,
    int lda, int ldb, int ldc, int K) {
    float acc[8];
    const int m0 = blockIdx.x * 64, n0 = blockIdx.y * 32;
    gemm_tile64x32(A, B, lda, ldb, K, m0, n0, acc);
    const int tn = threadIdx.x & 31, tg = threadIdx.x >> 5;
    const float bb = bias[n0 + tn];
    #pragma unroll
    for (int q = 0; q < 8; ++q) {
        float v = acc[q] + bb;
        C[(size_t)(m0 + tg * 8 + q) * ldc + n0 + tn] =
            0.5f * v * (1.0f + erff(v * 0.70710678118654752f));
    }
}

__global__ __launch_bounds__(256) void attnv_kernel(
    const float* __restrict__ scores, const float* __restrict__ nq,
    float* __restrict__ ao) {
    const int z = blockIdx.z, b = z >> 3, h = z & 7;
    const float* A = scores + (size_t)z * NN * NN;
    const float* B = nq + (size_t)b * NN * DD + h * 32;
    float acc[8];
    const int m0 = blockIdx.x * 64;
    gemm_tile64x32(A, B, NN, DD, NN, m0, 0, acc);
    const int tn = threadIdx.x & 31, tg = threadIdx.x >> 5;
    #pragma unroll
    for (int q = 0; q < 8; ++q)
        ao[((size_t)b * NN + (m0 + tg * 8 + q)) * DD + h * 32 + tn] = acc[q];
}

// ---------------- softmax (last dim 256, in place) ----------------
__global__ void softmax_kernel(float* __restrict__ sc) {
    __shared__ float sh[8];
    __shared__ float red;
    const size_t row = blockIdx.x;
    const int t = threadIdx.x;
    float v = sc[row * NN + t];
    float m = v;
    #pragma unroll
    for (int o = 16; o; o >>= 1) m = fmaxf(m, __shfl_xor_sync(0xffffffffu, m, o));
    if ((t & 31) == 0) sh[t >> 5] = m;
    __syncthreads();
    if (t == 0) {
        float mm = sh[0];
        #pragma unroll
        for (int w = 1; w < 8; ++w) mm = fmaxf(mm, sh[w]);
        red = mm;
    }
    __syncthreads();
    m = red;
    float e = expf(v - m);
    float s = e;
    #pragma unroll
    for (int o = 16; o; o >>= 1) s += __shfl_xor_sync(0xffffffffu, s, o);
    __syncthreads();
    if ((t & 31) == 0) sh[t >> 5] = s;
    __syncthreads();
    if (t == 0) {
        float ss = 0.f;
        #pragma unroll
        for (int w = 0; w < 8; ++w) ss += sh[w];
        red = 1.0f / ss;
    }
    __syncthreads();
    sc[row * NN + t] = e * red;
}

extern "C" void kernel_launch(void* const* d_in, const int* in_sizes, int n_in,
                              void* d_out, int out_size) {
    const float* nodes = (const float*)d_in[0];
    const float* edges = (const float*)d_in[1];
    const float* W     = (const float*)d_in[2];
    const float* b     = (const float*)d_in[3];
    const float* ln_g  = (const float*)d_in[4];
    const float* ln_b  = (const float*)d_in[5];
    const float* W1    = (const float*)d_in[6];
    const float* b1    = (const float*)d_in[7];
    const float* W2    = (const float*)d_in[8];
    const float* b2    = (const float*)d_in[9];
    float* out = (float*)d_out;

    float *px, *pnq, *psc, *pao, *pr, *px2, *phg;
    __half *pwq;
    cudaGetSymbolAddress((void**)&px,  g_x);
    cudaGetSymbolAddress((void**)&pnq, g_nq);
    cudaGetSymbolAddress((void**)&psc, g_sc);
    cudaGetSymbolAddress((void**)&pao, g_ao);
    cudaGetSymbolAddress((void**)&pr,  g_r);
    cudaGetSymbolAddress((void**)&px2, g_x2);
    cudaGetSymbolAddress((void**)&phg, g_hg);
    cudaGetSymbolAddress((void**)&pwq, g_wq);

    cudaFuncSetAttribute(edge_mma_kernel,
                         cudaFuncAttributeMaxDynamicSharedMemorySize, EDGE_SMEM);

    prep_w<<<64, 256>>>(W, pwq);   // FIX: 16384 pack units (was 4096 -> c always 0)
    ln_kernel<<<NB * NN, 256>>>(nodes, ln_g, ln_b, px);
    gemm_bias<<<dim3(8, 8), 256>>>(px, W, b, pnq, DD, DD, DD, DD);
    edge_mma_kernel<<<dim3(2, NN, NB), 256, EDGE_SMEM>>>(edges, pwq, b, pnq, psc);
    softmax_kernel<<<NB * NH * NN, 256>>>(psc);
    attnv_kernel<<<dim3(4, 1, NB * NH), 256>>>(psc, pnq, pao);
    gemm_bias_res<<<dim3(8, 8), 256>>>(pao, W, b, px, pr, DD, DD, DD, DD);
    ln_kernel<<<NB * NN, 256>>>(pr, ln_g, ln_b, px2);
    gemm_gelu<<<dim3(8, 32), 256>>>(px2, W1, b1, phg, DD, FFD, FFD, DD);
    gemm_bias_res<<<dim3(8, 8), 256>>>(phg, W2, b2, px2, out, FFD, DD, DD, FFD);
}

// round 10
// speedup vs baseline: 1.5136x; 1.0796x over previous
#include <cuda_runtime.h>
#include <cuda_fp16.h>
#include <cuda_bf16.h>
#include <math.h>
#include <stdint.h>

#define NB 2
#define NN 256
#define DD 256
#define NH 8
#define FFD 1024

// ---------------- scratch (static device globals) ----------------
__device__ float g_x [NB*NN*DD];
__device__ float g_nq[NB*NN*DD];
__device__ float g_sc[(size_t)NB*NH*NN*NN];
__device__ float g_ao[NB*NN*DD];
__device__ float g_r [NB*NN*DD];
__device__ float g_x2[NB*NN*DD];
__device__ float g_hg[NB*NN*FFD];
__device__ __half g_wq[4*256*128];   // packed W fragments: 256 KB

// ---------------- cp.async helpers ----------------
__device__ __forceinline__ uint32_t smem_u32(const void* p) {
    uint32_t a;
    asm("{ .reg .u64 t; cvta.to.shared.u64 t, %1; cvt.u32.u64 %0, t; }" : "=r"(a) : "l"(p));
    return a;
}
#define CP16(dst, src) \
    asm volatile("cp.async.cg.shared.global [%0], [%1], 16;" :: "r"(dst), "l"(src))
#define CP_COMMIT() asm volatile("cp.async.commit_group;" ::: "memory")
#define CP_WAIT(n)  asm volatile("cp.async.wait_group %0;" :: "n"(n) : "memory")

// ---------------- mma.sync m16n8k16 fp16 -> fp32 ----------------
__device__ __forceinline__ void mma16816(float* acc, uint32_t a0, uint32_t a1,
                                         uint32_t a2, uint32_t a3,
                                         uint32_t b0, uint32_t b1) {
    asm volatile(
        "mma.sync.aligned.m16n8k16.row.col.f32.f16.f16.f32 "
        "{%0,%1,%2,%3}, {%4,%5,%6,%7}, {%8,%9}, {%0,%1,%2,%3};"
        : "+f"(acc[0]), "+f"(acc[1]), "+f"(acc[2]), "+f"(acc[3])
        : "r"(a0), "r"(a1), "r"(a2), "r"(a3), "r"(b0), "r"(b1));
}

__device__ __forceinline__ void split_f2(float2 v, uint32_t &hi, uint32_t &lo) {
    __half hx = __float2half_rn(v.x), hy = __float2half_rn(v.y);
    __half lx = __float2half_rn(v.x - __half2float(hx));
    __half ly = __float2half_rn(v.y - __half2float(hy));
    hi = (uint32_t)__half_as_ushort(hx) | ((uint32_t)__half_as_ushort(hy) << 16);
    lo = (uint32_t)__half_as_ushort(lx) | ((uint32_t)__half_as_ushort(ly) << 16);
}

// ---------------- prep W: pack W^T hi/lo into fragment-friendly 16B units ----
// unit(c, n, s, p): halves [hi(ka),hi(ka+1),hi(ka+8),hi(ka+9), lo same] where
// ka = c*64 + s*16 + p*2, element = W[ka + delta][n].  16384 units total.
__global__ void prep_w(const float* __restrict__ W, __half* __restrict__ wq) {
    int id = blockIdx.x * 256 + threadIdx.x;     // 16384
    int p = id & 3, s = (id >> 2) & 3, n = (id >> 4) & 255, c = id >> 12;
    int ka = c * 64 + s * 16 + p * 2;
    __half u[8];
    #pragma unroll
    for (int q = 0; q < 4; ++q) {
        int k = ka + (q >> 1) * 8 + (q & 1);
        float v = W[k * 256 + n];
        __half h = __float2half_rn(v);
        u[q] = h;
        u[q + 4] = __float2half_rn(v - __half2float(h));
    }
    *(uint4*)(wq + (size_t)id * 8) = *(uint4*)u;
}

// ---------------- fused edge GEMM (mma.sync fp16x3) + score epilogue -------
// grid (jt=2, i=256, b=2), 512 threads (16 warps). CTA: 128 rows x 256 cols.
// Warp (wr = w&3, wc = w>>2): rows wr*32..+31 (2 m16 tiles), cols wc*64..+63.
#define A_PITCH 288
#define A_STAGE (128*A_PITCH)        // 36864
#define B_STAGE 65536                // 256 n x 256B, XOR-swizzled
#define B_BASE  (2*A_STAGE)
#define MISC    (B_BASE + 2*B_STAGE) // 204800
#define EDGE_SMEM (MISC + 2048)

__global__ __launch_bounds__(512, 1) void edge_mma_kernel(
    const float* __restrict__ edges, const __half* __restrict__ wq,
    const float* __restrict__ bias, const float* __restrict__ nq,
    float* __restrict__ scores) {
    extern __shared__ char smem[];
    const uint32_t sb = smem_u32(smem);
    const int t = threadIdx.x, lane = t & 31, w = t >> 5;
    const int qp = lane & 3, lg = lane >> 2;
    const int wr = w & 3, wc = w >> 2;
    const int jt = blockIdx.x, i = blockIdx.y, b = blockIdx.z;
    const size_t r0 = ((size_t)(b * NN + i)) * NN + jt * 128;
    const char* eg = (const char*)(edges + r0 * DD);
    const char* wg = (const char*)wq;

    // stage bias + nq_i
    float* sBias = (float*)(smem + MISC);
    float* sNqi  = sBias + 256;
    if (t < 256) {
        sBias[t] = bias[t];
        sNqi[t]  = nq[((size_t)(b * NN + i)) * DD + t];
    }

    // prefetch chunks 0,1
    #pragma unroll
    for (int c = 0; c < 2; ++c) {
        uint32_t a_s = sb + c * A_STAGE;
        #pragma unroll
        for (int it = 0; it < 4; ++it) {
            int u = t + 512 * it, row = u >> 4, part = u & 15;
            CP16(a_s + row * A_PITCH + part * 16,
                 eg + (size_t)row * 1024 + c * 256 + part * 16);
        }
        uint32_t b_s = sb + B_BASE + c * B_STAGE;
        #pragma unroll
        for (int it = 0; it < 8; ++it) {
            int u = t + 512 * it, n = u >> 4, unit = u & 15;
            int swz = (unit ^ ((n & 3) << 2)) & 15;
            CP16(b_s + n * 256 + swz * 16, wg + c * 65536 + n * 256 + unit * 16);
        }
        CP_COMMIT();
    }

    float acc[64];                       // [m(2)][nt(8)][4]
    #pragma unroll
    for (int q = 0; q < 64; ++q) acc[q] = 0.f;

    const int rbase = wr * 32 + lg;      // m-tile 0 row (m-tile 1 = +16)

    for (int c = 0; c < 4; ++c) {
        if (c < 3) { CP_WAIT(1); } else { CP_WAIT(0); }
        __syncthreads();
        const int buf = c & 1;
        const char* abase = smem + buf * A_STAGE;
        const char* bbase = smem + B_BASE + buf * B_STAGE;

        #pragma unroll
        for (int s = 0; s < 4; ++s) {
            // A fragments for both m-tiles
            uint32_t AH[2][4], AL[2][4];
            #pragma unroll
            for (int m = 0; m < 2; ++m) {
                const char* ar = abase + (rbase + m * 16) * A_PITCH + s * 64 + qp * 8;
                float2 va = *(const float2*)(ar);
                float2 vb = *(const float2*)(ar + 8 * A_PITCH);
                float2 vc = *(const float2*)(ar + 32);
                float2 vd = *(const float2*)(ar + 8 * A_PITCH + 32);
                split_f2(va, AH[m][0], AL[m][0]);
                split_f2(vb, AH[m][1], AL[m][1]);
                split_f2(vc, AH[m][2], AL[m][2]);
                split_f2(vd, AH[m][3], AL[m][3]);
            }
            const int swzoff = (((s * 4 + qp) ^ ((lg & 3) << 2)) & 15) * 16;
            #pragma unroll
            for (int nt = 0; nt < 8; ++nt) {
                const int n = wc * 64 + nt * 8 + lg;
                uint4 v = *(const uint4*)(bbase + n * 256 + swzoff);
                #pragma unroll
                for (int m = 0; m < 2; ++m) {
                    float* ac = &acc[(m * 8 + nt) * 4];
                    mma16816(ac, AH[m][0], AH[m][1], AH[m][2], AH[m][3], v.x, v.y);
                    mma16816(ac, AH[m][0], AH[m][1], AH[m][2], AH[m][3], v.z, v.w);
                    mma16816(ac, AL[m][0], AL[m][1], AL[m][2], AL[m][3], v.x, v.y);
                }
            }
        }
        __syncthreads();
        if (c < 2) {   // stage chunk c+2 into buf
            int cn = c + 2;
            uint32_t a_s = sb + buf * A_STAGE;
            #pragma unroll
            for (int it = 0; it < 4; ++it) {
                int u = t + 512 * it, row = u >> 4, part = u & 15;
                CP16(a_s + row * A_PITCH + part * 16,
                     eg + (size_t)row * 1024 + cn * 256 + part * 16);
            }
            uint32_t b_s = sb + B_BASE + buf * B_STAGE;
            #pragma unroll
            for (int it = 0; it < 8; ++it) {
                int u = t + 512 * it, n = u >> 4, unit = u & 15;
                int swz = (unit ^ ((n & 3) << 2)) & 15;
                CP16(b_s + n * 256 + swz * 16, wg + cn * 65536 + n * 256 + unit * 16);
            }
            CP_COMMIT();
        }
    }

    // epilogue: per-head score reduction
    const float* nqb = nq + ((size_t)b * NN) * DD;
    const float invs = 0.17677669529663687f;   // 1/sqrt(32)
    #pragma unroll
    for (int m = 0; m < 2; ++m) {
        const int jb = jt * 128 + wr * 32 + m * 16 + lg;
        #pragma unroll
        for (int hh = 0; hh < 2; ++hh) {
            const int h = wc * 2 + hh;
            float s1 = 0.f, s2 = 0.f;
            #pragma unroll
            for (int k = 0; k < 4; ++k) {
                const int nt = hh * 4 + k;
                const int col = wc * 64 + nt * 8 + qp * 2;
                const float* a = &acc[(m * 8 + nt) * 4];
                float2 q1 = *(const float2*)(nqb + (size_t)jb * DD + col);
                float2 q2 = *(const float2*)(nqb + (size_t)(jb + 8) * DD + col);
                float bi0 = sBias[col], bi1 = sBias[col + 1];
                float ni0 = sNqi[col],  ni1 = sNqi[col + 1];
                float e;
                e = a[0] + bi0; s1 += (e + ni0) * (e + q1.x);
                e = a[1] + bi1; s1 += (e + ni1) * (e + q1.y);
                e = a[2] + bi0; s2 += (e + ni0) * (e + q2.x);
                e = a[3] + bi1; s2 += (e + ni1) * (e + q2.y);
            }
            s1 += __shfl_xor_sync(0xffffffffu, s1, 1);
            s1 += __shfl_xor_sync(0xffffffffu, s1, 2);
            s2 += __shfl_xor_sync(0xffffffffu, s2, 1);
            s2 += __shfl_xor_sync(0xffffffffu, s2, 2);
            if (qp == 0) {
                float* sp = scores + (((size_t)(b * NH + h)) << 16) + (size_t)i * NN;
                sp[jb]     = 10.0f * tanhf(s1 * invs);
                sp[jb + 8] = 10.0f * tanhf(s2 * invs);
            }
        }
    }
}

// ---------------- LayerNorm ----------------
__global__ void ln_kernel(const float* __restrict__ in,
                          const float* __restrict__ gam,
                          const float* __restrict__ bet,
                          float* __restrict__ out) {
    __shared__ float sh[16];
    __shared__ float stats[2];
    const int row = blockIdx.x, t = threadIdx.x;
    float v = in[(size_t)row * DD + t];
    float s = v, sq = v * v;
    #pragma unroll
    for (int o = 16; o; o >>= 1) {
        s  += __shfl_down_sync(0xffffffffu, s,  o);
        sq += __shfl_down_sync(0xffffffffu, sq, o);
    }
    if ((t & 31) == 0) { sh[t >> 5] = s; sh[(t >> 5) + 8] = sq; }
    __syncthreads();
    if (t == 0) {
        float ts = 0.f, tq = 0.f;
        #pragma unroll
        for (int k = 0; k < 8; ++k) { ts += sh[k]; tq += sh[k + 8]; }
        float mu = ts * (1.0f / 256.0f);
        float var = tq * (1.0f / 256.0f) - mu * mu;
        stats[0] = mu; stats[1] = rsqrtf(var + 1e-5f);
    }
    __syncthreads();
    out[(size_t)row * DD + t] = (v - stats[0]) * stats[1] * gam[t] + bet[t];
}

// ---------------- fp32 64x32 GEMM tile for the small GEMMs ----------------
__device__ __forceinline__ void gemm_tile64x32(
    const float* __restrict__ A, const float* __restrict__ B,
    int lda, int ldb, int K, int m0, int n0, float acc[8]) {
    __shared__ __align__(16) float AsT[32][68];
    __shared__ float Bs[32][33];
    const int t = threadIdx.x, tn = t & 31, tg = t >> 5;
    #pragma unroll
    for (int q = 0; q < 8; ++q) acc[q] = 0.f;
    for (int k0 = 0; k0 < K; k0 += 32) {
        #pragma unroll
        for (int ph = 0; ph < 2; ++ph) {
            int flat = t + 256 * ph;
            int m = flat >> 3, kc = (flat & 7) << 2;
            float4 av = *(const float4*)(A + (size_t)(m0 + m) * lda + k0 + kc);
            AsT[kc + 0][m] = av.x; AsT[kc + 1][m] = av.y;
            AsT[kc + 2][m] = av.z; AsT[kc + 3][m] = av.w;
        }
        {
            int kr = t >> 3, nc = (t & 7) << 2;
            float4 bv = *(const float4*)(B + (size_t)(k0 + kr) * ldb + n0 + nc);
            Bs[kr][nc + 0] = bv.x; Bs[kr][nc + 1] = bv.y;
            Bs[kr][nc + 2] = bv.z; Bs[kr][nc + 3] = bv.w;
        }
        __syncthreads();
        #pragma unroll
        for (int kk = 0; kk < 32; ++kk) {
            float4 a0 = *(const float4*)&AsT[kk][tg * 8];
            float4 a1 = *(const float4*)&AsT[kk][tg * 8 + 4];
            float bb = Bs[kk][tn];
            acc[0] = fmaf(a0.x, bb, acc[0]); acc[1] = fmaf(a0.y, bb, acc[1]);
            acc[2] = fmaf(a0.z, bb, acc[2]); acc[3] = fmaf(a0.w, bb, acc[3]);
            acc[4] = fmaf(a1.x, bb, acc[4]); acc[5] = fmaf(a1.y, bb, acc[5]);
            acc[6] = fmaf(a1.z, bb, acc[6]); acc[7] = fmaf(a1.w, bb, acc[7]);
        }
        __syncthreads();
    }
}

__global__ __launch_bounds__(256) void gemm_bias(
    const float* __restrict__ A, const float* __restrict__ B,
    const float* __restrict__ bias, float* __restrict__ C,
    int lda, int ldb, int ldc, int K) {
    float acc[8];
    const int m0 = blockIdx.x * 64, n0 = blockIdx.y * 32;
    gemm_tile64x32(A, B, lda, ldb, K, m0, n0, acc);
    const int tn = threadIdx.x & 31, tg = threadIdx.x >> 5;
    const float bb = bias[n0 + tn];
    #pragma unroll
    for (int q = 0; q < 8; ++q)
        C[(size_t)(m0 + tg * 8 + q) * ldc + n0 + tn] = acc[q] + bb;
}

__global__ __launch_bounds__(256) void gemm_bias_res(
    const float* __restrict__ A, const float* __restrict__ B,
    const float* __restrict__ bias, const float* __restrict__ R,
    float* __restrict__ C, int lda, int ldb, int ldc, int K) {
    float acc[8];
    const int m0 = blockIdx.x * 64, n0 = blockIdx.y * 32;
    gemm_tile64x32(A, B, lda, ldb, K, m0, n0, acc);
    const int tn = threadIdx.x & 31, tg = threadIdx.x >> 5;
    const float bb = bias[n0 + tn];
    #pragma unroll
    for (int q = 0; q < 8; ++q) {
        size_t idx = (size_t)(m0 + tg * 8 + q) * ldc + n0 + tn;
        C[idx] = acc[q] + bb + R[idx];
    }
}

__global__ __launch_bounds__(256) void gemm_gelu(
    const float* __restrict__ A, const float* __restrict__ B,
    const float* __restrict__ bias, float* __restrict__ C,
    int lda, int ldb, int ldc, int K) {
    float acc[8];
    const int m0 = blockIdx.x * 64, n0 = blockIdx.y * 32;
    gemm_tile64x32(A, B, lda, ldb, K, m0, n0, acc);
    const int tn = threadIdx.x & 31, tg = threadIdx.x >> 5;
    const float bb = bias[n0 + tn];
    #pragma unroll
    for (int q = 0; q < 8; ++q) {
        float v = acc[q] + bb;
        C[(size_t)(m0 + tg * 8 + q) * ldc + n0 + tn] =
            0.5f * v * (1.0f + erff(v * 0.70710678118654752f));
    }
}

__global__ __launch_bounds__(256) void attnv_kernel(
    const float* __restrict__ scores, const float* __restrict__ nq,
    float* __restrict__ ao) {
    const int z = blockIdx.z, b = z >> 3, h = z & 7;
    const float* A = scores + (size_t)z * NN * NN;
    const float* B = nq + (size_t)b * NN * DD + h * 32;
    float acc[8];
    const int m0 = blockIdx.x * 64;
    gemm_tile64x32(A, B, NN, DD, NN, m0, 0, acc);
    const int tn = threadIdx.x & 31, tg = threadIdx.x >> 5;
    #pragma unroll
    for (int q = 0; q < 8; ++q)
        ao[((size_t)b * NN + (m0 + tg * 8 + q)) * DD + h * 32 + tn] = acc[q];
}

// ---------------- softmax (last dim 256, in place) ----------------
__global__ void softmax_kernel(float* __restrict__ sc) {
    __shared__ float sh[8];
    __shared__ float red;
    const size_t row = blockIdx.x;
    const int t = threadIdx.x;
    float v = sc[row * NN + t];
    float m = v;
    #pragma unroll
    for (int o = 16; o; o >>= 1) m = fmaxf(m, __shfl_xor_sync(0xffffffffu, m, o));
    if ((t & 31) == 0) sh[t >> 5] = m;
    __syncthreads();
    if (t == 0) {
        float mm = sh[0];
        #pragma unroll
        for (int w = 1; w < 8; ++w) mm = fmaxf(mm, sh[w]);
        red = mm;
    }
    __syncthreads();
    m = red;
    float e = expf(v - m);
    float s = e;
    #pragma unroll
    for (int o = 16; o; o >>= 1) s += __shfl_xor_sync(0xffffffffu, s, o);
    __syncthreads();
    if ((t & 31) == 0) sh[t >> 5] = s;
    __syncthreads();
    if (t == 0) {
        float ss = 0.f;
        #pragma unroll
        for (int w = 0; w < 8; ++w) ss += sh[w];
        red = 1.0f / ss;
    }
    __syncthreads();
    sc[row * NN + t] = e * red;
}

extern "C" void kernel_launch(void* const* d_in, const int* in_sizes, int n_in,
                              void* d_out, int out_size) {
    const float* nodes = (const float*)d_in[0];
    const float* edges = (const float*)d_in[1];
    const float* W     = (const float*)d_in[2];
    const float* b     = (const float*)d_in[3];
    const float* ln_g  = (const float*)d_in[4];
    const float* ln_b  = (const float*)d_in[5];
    const float* W1    = (const float*)d_in[6];
    const float* b1    = (const float*)d_in[7];
    const float* W2    = (const float*)d_in[8];
    const float* b2    = (const float*)d_in[9];
    float* out = (float*)d_out;

    float *px, *pnq, *psc, *pao, *pr, *px2, *phg;
    __half *pwq;
    cudaGetSymbolAddress((void**)&px,  g_x);
    cudaGetSymbolAddress((void**)&pnq, g_nq);
    cudaGetSymbolAddress((void**)&psc, g_sc);
    cudaGetSymbolAddress((void**)&pao, g_ao);
    cudaGetSymbolAddress((void**)&pr,  g_r);
    cudaGetSymbolAddress((void**)&px2, g_x2);
    cudaGetSymbolAddress((void**)&phg, g_hg);
    cudaGetSymbolAddress((void**)&pwq, g_wq);

    cudaFuncSetAttribute(edge_mma_kernel,
                         cudaFuncAttributeMaxDynamicSharedMemorySize, EDGE_SMEM);

    prep_w<<<64, 256>>>(W, pwq);
    ln_kernel<<<NB * NN, 256>>>(nodes, ln_g, ln_b, px);
    gemm_bias<<<dim3(8, 8), 256>>>(px, W, b, pnq, DD, DD, DD, DD);
    edge_mma_kernel<<<dim3(2, NN, NB), 512, EDGE_SMEM>>>(edges, pwq, b, pnq, psc);
    softmax_kernel<<<NB * NH * NN, 256>>>(psc);
    attnv_kernel<<<dim3(4, 1, NB * NH), 256>>>(psc, pnq, pao);
    gemm_bias_res<<<dim3(8, 8), 256>>>(pao, W, b, px, pr, DD, DD, DD, DD);
    ln_kernel<<<NB * NN, 256>>>(pr, ln_g, ln_b, px2);
    gemm_gelu<<<dim3(8, 32), 256>>>(px2, W1, b1, phg, DD, FFD, FFD, DD);
    gemm_bias_res<<<dim3(8, 8), 256>>>(phg, W2, b2, px2, out, FFD, DD, DD, FFD);
}